// round 7
// baseline (speedup 1.0000x reference)
#include <cuda_runtime.h>
#include <cuda_bf16.h>
#include <cstdint>

// ---------------- problem constants (gpt-small) ----------------
#define LAYERS 8
#define HEADS  8
#define CDIM   256
#define VDIM   128
#define TSEQ   1024
#define BATCH  32
#define DHEAD  32
#define FFDIM  1024
#define NTOK   (BATCH * TSEQ)        // 32768

// ---------------- scratch (static device allocations) ----------------
__device__ float g_x  [(size_t)NTOK * CDIM];            // residual stream (fp32)
__device__ __nv_bfloat16 g_qkvh[(size_t)NTOK * 3 * CDIM];
__device__ __nv_bfloat16 g_qkvl[(size_t)NTOK * 3 * CDIM];
__device__ __nv_bfloat16 g_hh[(size_t)NTOK * CDIM];
__device__ __nv_bfloat16 g_hl[(size_t)NTOK * CDIM];
__device__ __nv_bfloat16 g_yh[(size_t)NTOK * CDIM];
__device__ __nv_bfloat16 g_yl[(size_t)NTOK * CDIM];
__device__ __nv_bfloat16 g_gh[(size_t)NTOK * FFDIM];
__device__ __nv_bfloat16 g_gl[(size_t)NTOK * FFDIM];
// transposed/split weights [N,K] bf16 hi/lo
__device__ __nv_bfloat16 g_wqkvT_h[(size_t)LAYERS * 3 * CDIM * CDIM];
__device__ __nv_bfloat16 g_wqkvT_l[(size_t)LAYERS * 3 * CDIM * CDIM];
__device__ __nv_bfloat16 g_woT_h  [(size_t)LAYERS * CDIM * CDIM];
__device__ __nv_bfloat16 g_woT_l  [(size_t)LAYERS * CDIM * CDIM];
__device__ __nv_bfloat16 g_wfcT_h [(size_t)LAYERS * FFDIM * CDIM];
__device__ __nv_bfloat16 g_wfcT_l [(size_t)LAYERS * FFDIM * CDIM];
__device__ __nv_bfloat16 g_wprT_h [(size_t)LAYERS * CDIM * FFDIM];
__device__ __nv_bfloat16 g_wprT_l [(size_t)LAYERS * CDIM * FFDIM];
__device__ __nv_bfloat16 g_wlmT_h [(size_t)VDIM * CDIM];
__device__ __nv_bfloat16 g_wlmT_l [(size_t)VDIM * CDIM];

// ---------------- low-level helpers ----------------
__device__ __forceinline__ uint32_t smem_to_u32(const void* p) {
    uint32_t a;
    asm("{ .reg .u64 t; cvta.to.shared.u64 t, %1; cvt.u32.u64 %0, t; }" : "=r"(a) : "l"(p));
    return a;
}
__device__ __forceinline__ void cp16(uint32_t s, const void* g) {
    asm volatile("cp.async.ca.shared.global [%0], [%1], 16;" :: "r"(s), "l"(g) : "memory");
}
#define CP_COMMIT() asm volatile("cp.async.commit_group;" ::: "memory")
#define CP_WAIT0()  asm volatile("cp.async.wait_group 0;" ::: "memory")

__device__ __forceinline__ void ldm4(uint32_t a, uint32_t& r0, uint32_t& r1,
                                     uint32_t& r2, uint32_t& r3) {
    asm volatile("ldmatrix.sync.aligned.m8n8.x4.shared.b16 {%0,%1,%2,%3}, [%4];"
        : "=r"(r0), "=r"(r1), "=r"(r2), "=r"(r3) : "r"(a));
}
__device__ __forceinline__ void ldm4t(uint32_t a, uint32_t& r0, uint32_t& r1,
                                      uint32_t& r2, uint32_t& r3) {
    asm volatile("ldmatrix.sync.aligned.m8n8.x4.trans.shared.b16 {%0,%1,%2,%3}, [%4];"
        : "=r"(r0), "=r"(r1), "=r"(r2), "=r"(r3) : "r"(a));
}
__device__ __forceinline__ void mma16816(float* c, const uint32_t* a, const uint32_t* b) {
    asm volatile("mma.sync.aligned.m16n8k16.row.col.f32.bf16.bf16.f32 "
        "{%0,%1,%2,%3}, {%4,%5,%6,%7}, {%8,%9}, {%0,%1,%2,%3};"
        : "+f"(c[0]), "+f"(c[1]), "+f"(c[2]), "+f"(c[3])
        : "r"(a[0]), "r"(a[1]), "r"(a[2]), "r"(a[3]), "r"(b[0]), "r"(b[1]));
}

// ---------------- math helpers ----------------
__device__ __forceinline__ float warp_sum(float v) {
    #pragma unroll
    for (int o = 16; o; o >>= 1) v += __shfl_xor_sync(0xFFFFFFFFu, v, o);
    return v;
}
__device__ __forceinline__ float ex2f(float x) {
    float y; asm("ex2.approx.f32 %0, %1;" : "=f"(y) : "f"(x)); return y;
}
__device__ __forceinline__ float tanh_fast(float x) {
    float y; asm("tanh.approx.f32 %0, %1;" : "=f"(y) : "f"(x)); return y;
}
__device__ __forceinline__ float gelu_f(float x) {
    float x3 = x * x * x;
    float u  = 0.7978845608028654f * fmaf(0.044715f, x3, x);
    return 0.5f * x * (1.0f + tanh_fast(u));
}
__device__ __forceinline__ void bf16split(float v, __nv_bfloat16& h, __nv_bfloat16& l) {
    h = __float2bfloat16(v);
    l = __float2bfloat16(v - __bfloat162float(h));
}
__device__ __forceinline__ void bfpack2(float a, float b, uint32_t& hi, uint32_t& lo) {
    __nv_bfloat16 ha, la, hb, lb;
    bf16split(a, ha, la);
    bf16split(b, hb, lb);
    __nv_bfloat162 H(ha, hb), L(la, lb);
    hi = *(uint32_t*)&H;
    lo = *(uint32_t*)&L;
}

// ---------------- batched weight transpose + bf16 hi/lo split ----------------
#define WS_T0_END 1536
#define WS_T1_END 2048
#define WS_T2_END 4096
#define WS_T3_END 6144
#define WS_TOTAL  6176

__global__ void wsplit_all(const float* __restrict__ wqkv, const float* __restrict__ wo,
                           const float* __restrict__ wfc,  const float* __restrict__ wpr,
                           const float* __restrict__ wlm,
                           __nv_bfloat16* qkvh, __nv_bfloat16* qkvl,
                           __nv_bfloat16* woh,  __nv_bfloat16* wol,
                           __nv_bfloat16* fch,  __nv_bfloat16* fcl,
                           __nv_bfloat16* prh,  __nv_bfloat16* prl,
                           __nv_bfloat16* lmh,  __nv_bfloat16* lml) {
    int bid = blockIdx.x;
    const float* W; __nv_bfloat16 *Th, *Tl;
    int K, N, bxc, tile;
    if (bid < WS_T0_END) {
        int layer = bid / 192; tile = bid % 192;
        K = CDIM; N = 3 * CDIM; bxc = 24;
        W  = wqkv + (size_t)layer * K * N;
        Th = qkvh + (size_t)layer * N * K; Tl = qkvl + (size_t)layer * N * K;
    } else if (bid < WS_T1_END) {
        int r = bid - WS_T0_END; int layer = r / 64; tile = r % 64;
        K = CDIM; N = CDIM; bxc = 8;
        W  = wo  + (size_t)layer * K * N;
        Th = woh + (size_t)layer * N * K; Tl = wol + (size_t)layer * N * K;
    } else if (bid < WS_T2_END) {
        int r = bid - WS_T1_END; int layer = r / 256; tile = r % 256;
        K = CDIM; N = FFDIM; bxc = 32;
        W  = wfc + (size_t)layer * K * N;
        Th = fch + (size_t)layer * N * K; Tl = fcl + (size_t)layer * N * K;
    } else if (bid < WS_T3_END) {
        int r = bid - WS_T2_END; int layer = r / 256; tile = r % 256;
        K = FFDIM; N = CDIM; bxc = 8;
        W  = wpr + (size_t)layer * K * N;
        Th = prh + (size_t)layer * N * K; Tl = prl + (size_t)layer * N * K;
    } else {
        tile = bid - WS_T3_END;
        K = CDIM; N = VDIM; bxc = 4;
        W = wlm; Th = lmh; Tl = lml;
    }
    int nx = (tile % bxc) * 32, kx = (tile / bxc) * 32;

    __shared__ float t[32][33];
    #pragma unroll
    for (int i = 0; i < 4; i++) {
        int k = kx + threadIdx.y + i * 8;
        t[threadIdx.y + i * 8][threadIdx.x] = W[(size_t)k * N + nx + threadIdx.x];
    }
    __syncthreads();
    #pragma unroll
    for (int i = 0; i < 4; i++) {
        int n = nx + threadIdx.y + i * 8;
        int k = kx + threadIdx.x;
        float v = t[threadIdx.x][threadIdx.y + i * 8];
        __nv_bfloat16 h, l; bf16split(v, h, l);
        Th[(size_t)n * K + k] = h;
        Tl[(size_t)n * K + k] = l;
    }
}

// ---------------- embedding ----------------
__global__ void embed_kernel(const int* __restrict__ idx,
                             const float* __restrict__ tok,
                             const float* __restrict__ pos,
                             float* __restrict__ x) {
    int i = blockIdx.x * blockDim.x + threadIdx.x;
    if (i >= NTOK * CDIM) return;
    int row = i >> 8;
    int c   = i & (CDIM - 1);
    int t   = row & (TSEQ - 1);
    x[i] = tok[(size_t)idx[row] * CDIM + c] + pos[(size_t)t * CDIM + c];
}

// ---------------- layernorm -> bf16 hi/lo pair ----------------
__global__ void ln_kernel(const float* __restrict__ x,
                          const float* __restrict__ g,
                          const float* __restrict__ b,
                          __nv_bfloat16* __restrict__ oh,
                          __nv_bfloat16* __restrict__ ol) {
    int row = blockIdx.x;
    int c   = threadIdx.x;
    float v = x[(size_t)row * CDIM + c];
    float s1 = warp_sum(v);
    float s2 = warp_sum(v * v);
    __shared__ float sh1[8], sh2[8];
    int w = c >> 5, lane = c & 31;
    if (lane == 0) { sh1[w] = s1; sh2[w] = s2; }
    __syncthreads();
    float t1 = 0.f, t2 = 0.f;
    #pragma unroll
    for (int i = 0; i < 8; i++) { t1 += sh1[i]; t2 += sh2[i]; }
    float mean = t1 * (1.0f / CDIM);
    float var  = t2 * (1.0f / CDIM) - mean * mean;
    float rstd = rsqrtf(var + 1e-5f);
    float o = (v - mean) * rstd * g[c] + b[c];
    __nv_bfloat16 h, l; bf16split(o, h, l);
    oh[(size_t)row * CDIM + c] = h;
    ol[(size_t)row * CDIM + c] = l;
}

// ---------------- mma.sync bf16x3 GEMM (one sync per K-chunk) ----------------
// MODE 0: plain fp32   2: +bias +residual fp32
// MODE 3: +bias GELU -> bf16 pair   4: +bias -> bf16 pair
#define GBM 128
#define GBN 128
#define GBK 32
#define ROWB 80
#define TILE_B (128 * ROWB)
#define STAGE_B (4 * TILE_B)
#define GSMEM (2 * STAGE_B)             // 81920 bytes

template<int MODE>
__global__ __launch_bounds__(256, 2)
void gemm_mma(const __nv_bfloat16* __restrict__ Ah, const __nv_bfloat16* __restrict__ Al,
              const __nv_bfloat16* __restrict__ Bh, const __nv_bfloat16* __restrict__ Bl,
              const float* __restrict__ bias, const float* __restrict__ res,
              float* __restrict__ outF,
              __nv_bfloat16* __restrict__ outH, __nv_bfloat16* __restrict__ outL,
              int K, int No)
{
    extern __shared__ char smem[];
    uint32_t sU = smem_to_u32(smem);
    int tid  = threadIdx.x;
    int wid  = tid >> 5, lane = tid & 31;
    int warp_m = wid & 3, warp_n = wid >> 2;
    int m0 = blockIdx.y * GBM, n0 = blockIdx.x * GBN;

    float C[2][8][4];
    #pragma unroll
    for (int mt = 0; mt < 2; mt++)
        #pragma unroll
        for (int nt = 0; nt < 8; nt++)
            #pragma unroll
            for (int k = 0; k < 4; k++) C[mt][nt][k] = 0.f;

    int lr0 = tid >> 2,  lc0 = (tid & 3);
    int lr1 = (tid + 256) >> 2, lc1 = ((tid + 256) & 3);

    int nch = K >> 5;
    auto load_stage = [&](int ch, int buf) {
        int k0 = ch * GBK;
        uint32_t sb = sU + buf * STAGE_B;
        {
            uint32_t so = lr0 * ROWB + lc0 * 16;
            cp16(sb + so,              Ah + (size_t)(m0 + lr0) * K + k0 + lc0 * 8);
            cp16(sb + TILE_B + so,     Al + (size_t)(m0 + lr0) * K + k0 + lc0 * 8);
            cp16(sb + 2 * TILE_B + so, Bh + (size_t)(n0 + lr0) * K + k0 + lc0 * 8);
            cp16(sb + 3 * TILE_B + so, Bl + (size_t)(n0 + lr0) * K + k0 + lc0 * 8);
        }
        {
            uint32_t so = lr1 * ROWB + lc1 * 16;
            cp16(sb + so,              Ah + (size_t)(m0 + lr1) * K + k0 + lc1 * 8);
            cp16(sb + TILE_B + so,     Al + (size_t)(m0 + lr1) * K + k0 + lc1 * 8);
            cp16(sb + 2 * TILE_B + so, Bh + (size_t)(n0 + lr1) * K + k0 + lc1 * 8);
            cp16(sb + 3 * TILE_B + so, Bl + (size_t)(n0 + lr1) * K + k0 + lc1 * 8);
        }
    };

    load_stage(0, 0);
    CP_COMMIT();

    int rin = lane & 7;
    int amat = lane >> 3;
    int bnt  = (lane >> 4) & 1;
    int bkh  = (lane >> 3) & 1;

    for (int ch = 0; ch < nch; ch++) {
        int buf = ch & 1;
        CP_WAIT0();
        __syncthreads();                          // data ready AND buf^1 free
        if (ch + 1 < nch) { load_stage(ch + 1, buf ^ 1); CP_COMMIT(); }

        uint32_t sA  = sU + buf * STAGE_B;
        uint32_t sAl = sA + TILE_B;
        uint32_t sBh = sA + 2 * TILE_B;
        uint32_t sBl = sA + 3 * TILE_B;

        #pragma unroll
        for (int s = 0; s < 2; s++) {
            uint32_t ah[2][4], al[2][4];
            #pragma unroll
            for (int mt = 0; mt < 2; mt++) {
                int row = warp_m * 32 + mt * 16 + (amat & 1) * 8 + rin;
                uint32_t off = row * ROWB + (amat >> 1) * 16 + s * 32;
                ldm4(sA  + off, ah[mt][0], ah[mt][1], ah[mt][2], ah[mt][3]);
                ldm4(sAl + off, al[mt][0], al[mt][1], al[mt][2], al[mt][3]);
            }
            #pragma unroll
            for (int g = 0; g < 4; g++) {
                int row = warp_n * 64 + g * 16 + bnt * 8 + rin;
                uint32_t off = row * ROWB + bkh * 16 + s * 32;
                uint32_t bh[4], bl[4];
                ldm4(sBh + off, bh[0], bh[1], bh[2], bh[3]);
                ldm4(sBl + off, bl[0], bl[1], bl[2], bl[3]);
                #pragma unroll
                for (int mt = 0; mt < 2; mt++) {
                    mma16816(C[mt][2*g],   ah[mt], &bh[0]);
                    mma16816(C[mt][2*g],   ah[mt], &bl[0]);
                    mma16816(C[mt][2*g],   al[mt], &bh[0]);
                    mma16816(C[mt][2*g+1], ah[mt], &bh[2]);
                    mma16816(C[mt][2*g+1], ah[mt], &bl[2]);
                    mma16816(C[mt][2*g+1], al[mt], &bh[2]);
                }
            }
        }
    }

    // ---- epilogue ----
    int rbase = m0 + warp_m * 32;
    int cbase = n0 + warp_n * 64;
    #pragma unroll
    for (int mt = 0; mt < 2; mt++) {
        #pragma unroll
        for (int nt = 0; nt < 8; nt++) {
            int row = rbase + mt * 16 + (lane >> 2);
            int col = cbase + nt * 8 + (lane & 3) * 2;
            const float* c = C[mt][nt];
            float2 b2 = make_float2(0.f, 0.f);
            if (MODE >= 2) b2 = *(const float2*)(bias + col);
            if (MODE == 3 || MODE == 4) {
                float g0 = c[0] + b2.x, g1 = c[1] + b2.y;
                float g2 = c[2] + b2.x, g3 = c[3] + b2.y;
                if (MODE == 3) { g0 = gelu_f(g0); g1 = gelu_f(g1); g2 = gelu_f(g2); g3 = gelu_f(g3); }
                uint32_t hi, lo;
                bfpack2(g0, g1, hi, lo);
                *(uint32_t*)(outH + (size_t)row * No + col) = hi;
                *(uint32_t*)(outL + (size_t)row * No + col) = lo;
                bfpack2(g2, g3, hi, lo);
                *(uint32_t*)(outH + (size_t)(row + 8) * No + col) = hi;
                *(uint32_t*)(outL + (size_t)(row + 8) * No + col) = lo;
            } else {
                float2 v0 = make_float2(c[0] + b2.x, c[1] + b2.y);
                float2 v1 = make_float2(c[2] + b2.x, c[3] + b2.y);
                if (MODE == 2) {
                    float2 r0 = *(const float2*)(res + (size_t)row * No + col);
                    float2 r1 = *(const float2*)(res + (size_t)(row + 8) * No + col);
                    v0.x += r0.x; v0.y += r0.y; v1.x += r1.x; v1.y += r1.y;
                }
                *(float2*)(outF + (size_t)row * No + col) = v0;
                *(float2*)(outF + (size_t)(row + 8) * No + col) = v1;
            }
        }
    }
}

// ---------------- flash attention on mma.sync, double-buffered K/V ----------------
#define AP 80
#define ATILE (64 * AP)            // 5120 bytes per 64x32 bf16 tile
#define ASTAGE (4 * ATILE)         // Kh,Kl,Vh,Vl = 20480
#define ASMEM (2 * ATILE + 2 * ASTAGE)   // Qh,Ql + 2 stages = 51200

__global__ __launch_bounds__(128)
void attn_mma(const __nv_bfloat16* __restrict__ qkvH,
              const __nv_bfloat16* __restrict__ qkvL,
              __nv_bfloat16* __restrict__ yh, __nv_bfloat16* __restrict__ yl)
{
    extern __shared__ __align__(16) char smA[];
    uint32_t sQ = smem_to_u32(smA);             // Qh, Ql
    uint32_t sS = sQ + 2 * ATILE;               // stage 0, stage 1
    int tid = threadIdx.x, wid = tid >> 5, lane = tid & 31;
    int b = blockIdx.y >> 3, h = blockIdx.y & 7;
    int q0 = blockIdx.x * 64;
    size_t tokbase = (size_t)b * TSEQ * 768;
    const float qs = 0.17677669529663687f * 1.4426950408889634f;

    int ntiles = blockIdx.x + 1;

    auto loadKV = [&](int kb, int st) {
        int j0 = kb * 64;
        uint32_t sb = sS + st * ASTAGE;
        #pragma unroll
        for (int i = 0; i < 8; i++) {
            int u = i * 128 + tid;
            int bufi = u >> 8;
            int c = u & 255, row = c >> 2, cc = c & 3;
            size_t g = tokbase + (size_t)(j0 + row) * 768 + h * DHEAD + cc * 8;
            const __nv_bfloat16* src;
            if      (bufi == 0) src = qkvH + g + CDIM;
            else if (bufi == 1) src = qkvL + g + CDIM;
            else if (bufi == 2) src = qkvH + g + 2 * CDIM;
            else                src = qkvL + g + 2 * CDIM;
            cp16(sb + bufi * ATILE + row * AP + cc * 16, src);
        }
    };

    // prologue: async K/V tile 0, plain Q stores
    loadKV(0, 0);
    CP_COMMIT();
    #pragma unroll
    for (int i = 0; i < 2; i++) {
        int u = tid + i * 128;
        int row = u >> 2, c = u & 3;
        size_t g = tokbase + (size_t)(q0 + row) * 768 + h * DHEAD + c * 8;
        *(uint4*)(smA + row * AP + c * 16)         = *(const uint4*)(qkvH + g);
        *(uint4*)(smA + ATILE + row * AP + c * 16) = *(const uint4*)(qkvL + g);
    }
    __syncthreads();
    uint32_t qh[2][4], ql[2][4];
    #pragma unroll
    for (int ks = 0; ks < 2; ks++) {
        uint32_t a = sQ + (wid * 16 + (lane & 15)) * AP + ks * 32 + (lane >> 4) * 16;
        ldm4(a,         qh[ks][0], qh[ks][1], qh[ks][2], qh[ks][3]);
        ldm4(a + ATILE, ql[ks][0], ql[ks][1], ql[ks][2], ql[ks][3]);
    }

    float O[4][4];
    #pragma unroll
    for (int i = 0; i < 4; i++)
        #pragma unroll
        for (int j = 0; j < 4; j++) O[i][j] = 0.f;
    float m0 = -1e30f, m1 = -1e30f, l0 = 0.f, l1 = 0.f;

    for (int kb = 0; kb < ntiles; kb++) {
        int st = kb & 1;
        CP_WAIT0();
        __syncthreads();                 // stage st ready; stage st^1 free
        if (kb + 1 < ntiles) { loadKV(kb + 1, st ^ 1); CP_COMMIT(); }
        uint32_t sK = sS + st * ASTAGE;

        // ---- S = Q K^T (bf16x3) ----
        float sc[8][4];
        #pragma unroll
        for (int nt = 0; nt < 8; nt++)
            #pragma unroll
            for (int j = 0; j < 4; j++) sc[nt][j] = 0.f;
        #pragma unroll
        for (int ks = 0; ks < 2; ks++) {
            #pragma unroll
            for (int g = 0; g < 4; g++) {
                uint32_t addr = sK + (g * 16 + ((lane >> 4) & 1) * 8 + (lane & 7)) * AP
                              + ks * 32 + ((lane >> 3) & 1) * 16;
                uint32_t kh[4], kl[4];
                ldm4(addr,         kh[0], kh[1], kh[2], kh[3]);
                ldm4(addr + ATILE, kl[0], kl[1], kl[2], kl[3]);
                mma16816(sc[2*g],   qh[ks], &kh[0]);
                mma16816(sc[2*g],   qh[ks], &kl[0]);
                mma16816(sc[2*g],   ql[ks], &kh[0]);
                mma16816(sc[2*g+1], qh[ks], &kh[2]);
                mma16816(sc[2*g+1], qh[ks], &kl[2]);
                mma16816(sc[2*g+1], ql[ks], &kh[2]);
            }
        }

        // ---- causal mask on diagonal tile ----
        if (kb == blockIdx.x) {
            int qr = wid * 16 + (lane >> 2);
            #pragma unroll
            for (int nt = 0; nt < 8; nt++) {
                int kc = nt * 8 + (lane & 3) * 2;
                if (kc     > qr)     sc[nt][0] = -1e30f;
                if (kc + 1 > qr)     sc[nt][1] = -1e30f;
                if (kc     > qr + 8) sc[nt][2] = -1e30f;
                if (kc + 1 > qr + 8) sc[nt][3] = -1e30f;
            }
        }

        // ---- online softmax (base-2) ----
        float rm0 = -1e30f, rm1 = -1e30f;
        #pragma unroll
        for (int nt = 0; nt < 8; nt++) {
            rm0 = fmaxf(rm0, fmaxf(sc[nt][0], sc[nt][1]));
            rm1 = fmaxf(rm1, fmaxf(sc[nt][2], sc[nt][3]));
        }
        rm0 = fmaxf(rm0, __shfl_xor_sync(0xFFFFFFFFu, rm0, 1));
        rm0 = fmaxf(rm0, __shfl_xor_sync(0xFFFFFFFFu, rm0, 2));
        rm1 = fmaxf(rm1, __shfl_xor_sync(0xFFFFFFFFu, rm1, 1));
        rm1 = fmaxf(rm1, __shfl_xor_sync(0xFFFFFFFFu, rm1, 2));
        float m0n = fmaxf(m0, rm0), m1n = fmaxf(m1, rm1);
        float c0 = ex2f((m0 - m0n) * qs), c1 = ex2f((m1 - m1n) * qs);
        m0 = m0n; m1 = m1n;
        float mq0 = m0 * qs, mq1 = m1 * qs;
        float rs0 = 0.f, rs1 = 0.f;
        #pragma unroll
        for (int nt = 0; nt < 8; nt++) {
            sc[nt][0] = ex2f(fmaf(sc[nt][0], qs, -mq0));
            sc[nt][1] = ex2f(fmaf(sc[nt][1], qs, -mq0));
            sc[nt][2] = ex2f(fmaf(sc[nt][2], qs, -mq1));
            sc[nt][3] = ex2f(fmaf(sc[nt][3], qs, -mq1));
            rs0 += sc[nt][0] + sc[nt][1];
            rs1 += sc[nt][2] + sc[nt][3];
        }
        rs0 += __shfl_xor_sync(0xFFFFFFFFu, rs0, 1);
        rs0 += __shfl_xor_sync(0xFFFFFFFFu, rs0, 2);
        rs1 += __shfl_xor_sync(0xFFFFFFFFu, rs1, 1);
        rs1 += __shfl_xor_sync(0xFFFFFFFFu, rs1, 2);
        l0 = l0 * c0 + rs0;
        l1 = l1 * c1 + rs1;
        #pragma unroll
        for (int nt = 0; nt < 4; nt++) {
            O[nt][0] *= c0; O[nt][1] *= c0;
            O[nt][2] *= c1; O[nt][3] *= c1;
        }

        // ---- O += P V (Ph*Vh + Ph*Vl + Pl*Vh) ----
        #pragma unroll
        for (int ks = 0; ks < 4; ks++) {
            uint32_t ph[4], pl[4];
            bfpack2(sc[2*ks][0],   sc[2*ks][1],   ph[0], pl[0]);
            bfpack2(sc[2*ks][2],   sc[2*ks][3],   ph[1], pl[1]);
            bfpack2(sc[2*ks+1][0], sc[2*ks+1][1], ph[2], pl[2]);
            bfpack2(sc[2*ks+1][2], sc[2*ks+1][3], ph[3], pl[3]);
            #pragma unroll
            for (int g = 0; g < 2; g++) {
                uint32_t addr = sK + 2 * ATILE
                              + (16 * ks + ((lane >> 3) & 1) * 8 + (lane & 7)) * AP
                              + g * 32 + (lane >> 4) * 16;
                uint32_t vh[4], vl[4];
                ldm4t(addr,         vh[0], vh[1], vh[2], vh[3]);
                ldm4t(addr + ATILE, vl[0], vl[1], vl[2], vl[3]);
                mma16816(O[2*g],   ph, &vh[0]);
                mma16816(O[2*g],   ph, &vl[0]);
                mma16816(O[2*g],   pl, &vh[0]);
                mma16816(O[2*g+1], ph, &vh[2]);
                mma16816(O[2*g+1], ph, &vl[2]);
                mma16816(O[2*g+1], pl, &vh[2]);
            }
        }
    }

    // ---- normalize + write bf16 hi/lo ----
    float i0 = 1.0f / l0, i1 = 1.0f / l1;
    int r0 = q0 + wid * 16 + (lane >> 2);
    #pragma unroll
    for (int nt = 0; nt < 4; nt++) {
        int col = h * DHEAD + nt * 8 + (lane & 3) * 2;
        size_t g0 = (size_t)(b * TSEQ + r0) * CDIM + col;
        size_t g1 = g0 + (size_t)8 * CDIM;
        uint32_t hi, lo;
        bfpack2(O[nt][0] * i0, O[nt][1] * i0, hi, lo);
        *(uint32_t*)(yh + g0) = hi;
        *(uint32_t*)(yl + g0) = lo;
        bfpack2(O[nt][2] * i1, O[nt][3] * i1, hi, lo);
        *(uint32_t*)(yh + g1) = hi;
        *(uint32_t*)(yl + g1) = lo;
    }
}

// ---------------- host orchestration (graph-capturable) ----------------
extern "C" void kernel_launch(void* const* d_in, const int* in_sizes, int n_in,
                              void* d_out, int out_size) {
    (void)in_sizes; (void)n_in; (void)out_size;
    const int*   idx   = (const int*)  d_in[0];
    const float* tok   = (const float*)d_in[1];
    const float* pos   = (const float*)d_in[2];
    const float* ln1g  = (const float*)d_in[3];
    const float* ln1b  = (const float*)d_in[4];
    const float* wqkv  = (const float*)d_in[5];
    const float* bqkv  = (const float*)d_in[6];
    const float* wo    = (const float*)d_in[7];
    const float* bo    = (const float*)d_in[8];
    const float* ln2g  = (const float*)d_in[9];
    const float* ln2b  = (const float*)d_in[10];
    const float* wfc   = (const float*)d_in[11];
    const float* bfc   = (const float*)d_in[12];
    const float* wpr   = (const float*)d_in[13];
    const float* bpr   = (const float*)d_in[14];
    const float* lnfg  = (const float*)d_in[15];
    const float* lnfb  = (const float*)d_in[16];
    const float* wlm   = (const float*)d_in[17];
    float* out = (float*)d_out;

    float *x;
    __nv_bfloat16 *qh, *ql_, *hh, *hl, *yh, *yl, *gh, *gl;
    __nv_bfloat16 *wqkvTh, *wqkvTl, *woTh, *woTl, *wfcTh, *wfcTl, *wprTh, *wprTl, *wlmTh, *wlmTl;
    cudaGetSymbolAddress((void**)&x,   g_x);
    cudaGetSymbolAddress((void**)&qh,  g_qkvh);
    cudaGetSymbolAddress((void**)&ql_, g_qkvl);
    cudaGetSymbolAddress((void**)&hh,  g_hh);
    cudaGetSymbolAddress((void**)&hl,  g_hl);
    cudaGetSymbolAddress((void**)&yh,  g_yh);
    cudaGetSymbolAddress((void**)&yl,  g_yl);
    cudaGetSymbolAddress((void**)&gh,  g_gh);
    cudaGetSymbolAddress((void**)&gl,  g_gl);
    cudaGetSymbolAddress((void**)&wqkvTh, g_wqkvT_h);
    cudaGetSymbolAddress((void**)&wqkvTl, g_wqkvT_l);
    cudaGetSymbolAddress((void**)&woTh,   g_woT_h);
    cudaGetSymbolAddress((void**)&woTl,   g_woT_l);
    cudaGetSymbolAddress((void**)&wfcTh,  g_wfcT_h);
    cudaGetSymbolAddress((void**)&wfcTl,  g_wfcT_l);
    cudaGetSymbolAddress((void**)&wprTh,  g_wprT_h);
    cudaGetSymbolAddress((void**)&wprTl,  g_wprT_l);
    cudaGetSymbolAddress((void**)&wlmTh,  g_wlmT_h);
    cudaGetSymbolAddress((void**)&wlmTl,  g_wlmT_l);

    cudaFuncSetAttribute(gemm_mma<0>, cudaFuncAttributeMaxDynamicSharedMemorySize, GSMEM);
    cudaFuncSetAttribute(gemm_mma<2>, cudaFuncAttributeMaxDynamicSharedMemorySize, GSMEM);
    cudaFuncSetAttribute(gemm_mma<3>, cudaFuncAttributeMaxDynamicSharedMemorySize, GSMEM);
    cudaFuncSetAttribute(gemm_mma<4>, cudaFuncAttributeMaxDynamicSharedMemorySize, GSMEM);
    cudaFuncSetAttribute(attn_mma, cudaFuncAttributeMaxDynamicSharedMemorySize, ASMEM);

    wsplit_all<<<WS_TOTAL, dim3(32, 8)>>>(
        wqkv, wo, wfc, wpr, wlm,
        wqkvTh, wqkvTl, woTh, woTl, wfcTh, wfcTl, wprTh, wprTl, wlmTh, wlmTl);

    embed_kernel<<<(NTOK * CDIM + 255) / 256, 256>>>(idx, tok, pos, x);

    dim3 gB(256);
    dim3 grid_qkv(3 * CDIM / GBN, NTOK / GBM);
    dim3 grid_prj(CDIM / GBN,     NTOK / GBM);
    dim3 grid_fc (FFDIM / GBN,    NTOK / GBM);
    dim3 grid_lm (VDIM / GBN,     NTOK / GBM);
    dim3 grid_att(TSEQ / 64, BATCH * HEADS);

    for (int l = 0; l < LAYERS; l++) {
        ln_kernel<<<NTOK, 256>>>(x, ln1g + l * CDIM, ln1b + l * CDIM, hh, hl);
        gemm_mma<4><<<grid_qkv, gB, GSMEM>>>(
            hh, hl,
            wqkvTh + (size_t)l * 3 * CDIM * CDIM, wqkvTl + (size_t)l * 3 * CDIM * CDIM,
            bqkv + (size_t)l * 3 * CDIM, nullptr, nullptr, qh, ql_,
            CDIM, 3 * CDIM);
        attn_mma<<<grid_att, 128, ASMEM>>>(qh, ql_, yh, yl);
        gemm_mma<2><<<grid_prj, gB, GSMEM>>>(
            yh, yl,
            woTh + (size_t)l * CDIM * CDIM, woTl + (size_t)l * CDIM * CDIM,
            bo + (size_t)l * CDIM, x, x, nullptr, nullptr,
            CDIM, CDIM);
        ln_kernel<<<NTOK, 256>>>(x, ln2g + l * CDIM, ln2b + l * CDIM, hh, hl);
        gemm_mma<3><<<grid_fc, gB, GSMEM>>>(
            hh, hl,
            wfcTh + (size_t)l * FFDIM * CDIM, wfcTl + (size_t)l * FFDIM * CDIM,
            bfc + (size_t)l * FFDIM, nullptr, nullptr, gh, gl,
            CDIM, FFDIM);
        gemm_mma<2><<<grid_prj, gB, GSMEM>>>(
            gh, gl,
            wprTh + (size_t)l * CDIM * FFDIM, wprTl + (size_t)l * CDIM * FFDIM,
            bpr + (size_t)l * CDIM, x, x, nullptr, nullptr,
            FFDIM, CDIM);
    }

    ln_kernel<<<NTOK, 256>>>(x, lnfg, lnfb, hh, hl);
    gemm_mma<0><<<grid_lm, gB, GSMEM>>>(
        hh, hl, wlmTh, wlmTl,
        nullptr, nullptr, out, nullptr, nullptr,
        CDIM, VDIM);
}

// round 8
// speedup vs baseline: 1.2916x; 1.2916x over previous
#include <cuda_runtime.h>
#include <cuda_fp16.h>
#include <cstdint>

// ---------------- problem constants (gpt-small) ----------------
#define LAYERS 8
#define HEADS  8
#define CDIM   256
#define VDIM   128
#define TSEQ   1024
#define BATCH  32
#define DHEAD  32
#define FFDIM  1024
#define NTOK   (BATCH * TSEQ)        // 32768

// ---------------- scratch (static device allocations) ----------------
__device__ float  g_x [(size_t)NTOK * CDIM];            // residual stream (fp32)
__device__ __half g_qkvh[(size_t)NTOK * 3 * CDIM];      // qkv hi (fp16)
__device__ __half g_qkvl[(size_t)NTOK * 3 * CDIM];      // qkv lo residual
__device__ __half g_h [(size_t)NTOK * CDIM];            // LN out (single fp16)
__device__ __half g_y [(size_t)NTOK * CDIM];            // attn out (single fp16)
__device__ __half g_g [(size_t)NTOK * FFDIM];           // gelu out (single fp16)
// transposed/split weights [N,K] fp16 hi/lo
__device__ __half g_wqkvT_h[(size_t)LAYERS * 3 * CDIM * CDIM];
__device__ __half g_wqkvT_l[(size_t)LAYERS * 3 * CDIM * CDIM];
__device__ __half g_woT_h  [(size_t)LAYERS * CDIM * CDIM];
__device__ __half g_woT_l  [(size_t)LAYERS * CDIM * CDIM];
__device__ __half g_wfcT_h [(size_t)LAYERS * FFDIM * CDIM];
__device__ __half g_wfcT_l [(size_t)LAYERS * FFDIM * CDIM];
__device__ __half g_wprT_h [(size_t)LAYERS * CDIM * FFDIM];
__device__ __half g_wprT_l [(size_t)LAYERS * CDIM * FFDIM];
__device__ __half g_wlmT_h [(size_t)VDIM * CDIM];
__device__ __half g_wlmT_l [(size_t)VDIM * CDIM];

// ---------------- low-level helpers ----------------
__device__ __forceinline__ uint32_t smem_to_u32(const void* p) {
    uint32_t a;
    asm("{ .reg .u64 t; cvta.to.shared.u64 t, %1; cvt.u32.u64 %0, t; }" : "=r"(a) : "l"(p));
    return a;
}
__device__ __forceinline__ void cp16(uint32_t s, const void* g) {
    asm volatile("cp.async.ca.shared.global [%0], [%1], 16;" :: "r"(s), "l"(g) : "memory");
}
#define CP_COMMIT() asm volatile("cp.async.commit_group;" ::: "memory")
#define CP_WAIT1()  asm volatile("cp.async.wait_group 1;" ::: "memory")
#define CP_WAIT0()  asm volatile("cp.async.wait_group 0;" ::: "memory")

__device__ __forceinline__ void ldm4(uint32_t a, uint32_t& r0, uint32_t& r1,
                                     uint32_t& r2, uint32_t& r3) {
    asm volatile("ldmatrix.sync.aligned.m8n8.x4.shared.b16 {%0,%1,%2,%3}, [%4];"
        : "=r"(r0), "=r"(r1), "=r"(r2), "=r"(r3) : "r"(a));
}
__device__ __forceinline__ void ldm4t(uint32_t a, uint32_t& r0, uint32_t& r1,
                                      uint32_t& r2, uint32_t& r3) {
    asm volatile("ldmatrix.sync.aligned.m8n8.x4.trans.shared.b16 {%0,%1,%2,%3}, [%4];"
        : "=r"(r0), "=r"(r1), "=r"(r2), "=r"(r3) : "r"(a));
}
__device__ __forceinline__ void mma16816(float* c, const uint32_t* a, const uint32_t* b) {
    asm volatile("mma.sync.aligned.m16n8k16.row.col.f32.f16.f16.f32 "
        "{%0,%1,%2,%3}, {%4,%5,%6,%7}, {%8,%9}, {%0,%1,%2,%3};"
        : "+f"(c[0]), "+f"(c[1]), "+f"(c[2]), "+f"(c[3])
        : "r"(a[0]), "r"(a[1]), "r"(a[2]), "r"(a[3]), "r"(b[0]), "r"(b[1]));
}

// ---------------- math helpers ----------------
__device__ __forceinline__ float warp_sum(float v) {
    #pragma unroll
    for (int o = 16; o; o >>= 1) v += __shfl_xor_sync(0xFFFFFFFFu, v, o);
    return v;
}
__device__ __forceinline__ float ex2f(float x) {
    float y; asm("ex2.approx.f32 %0, %1;" : "=f"(y) : "f"(x)); return y;
}
__device__ __forceinline__ float tanh_fast(float x) {
    float y; asm("tanh.approx.f32 %0, %1;" : "=f"(y) : "f"(x)); return y;
}
__device__ __forceinline__ float gelu_f(float x) {
    float x3 = x * x * x;
    float u  = 0.7978845608028654f * fmaf(0.044715f, x3, x);
    return 0.5f * x * (1.0f + tanh_fast(u));
}
__device__ __forceinline__ void f16split(float v, __half& h, __half& l) {
    h = __float2half_rn(v);
    l = __float2half_rn(v - __half2float(h));
}
__device__ __forceinline__ void hpack2(float a, float b, uint32_t& hi, uint32_t& lo) {
    __half ha, la, hb, lb;
    f16split(a, ha, la);
    f16split(b, hb, lb);
    __half2 H = __halves2half2(ha, hb), L = __halves2half2(la, lb);
    hi = *(uint32_t*)&H;
    lo = *(uint32_t*)&L;
}
__device__ __forceinline__ uint32_t hpack(float a, float b) {
    __half2 H = __floats2half2_rn(a, b);
    return *(uint32_t*)&H;
}

// ---------------- batched weight transpose + fp16 hi/lo split ----------------
#define WS_T0_END 1536
#define WS_T1_END 2048
#define WS_T2_END 4096
#define WS_T3_END 6144
#define WS_TOTAL  6176

__global__ void wsplit_all(const float* __restrict__ wqkv, const float* __restrict__ wo,
                           const float* __restrict__ wfc,  const float* __restrict__ wpr,
                           const float* __restrict__ wlm,
                           __half* qkvh, __half* qkvl,
                           __half* woh,  __half* wol,
                           __half* fch,  __half* fcl,
                           __half* prh,  __half* prl,
                           __half* lmh,  __half* lml) {
    int bid = blockIdx.x;
    const float* W; __half *Th, *Tl;
    int K, N, bxc, tile;
    if (bid < WS_T0_END) {
        int layer = bid / 192; tile = bid % 192;
        K = CDIM; N = 3 * CDIM; bxc = 24;
        W  = wqkv + (size_t)layer * K * N;
        Th = qkvh + (size_t)layer * N * K; Tl = qkvl + (size_t)layer * N * K;
    } else if (bid < WS_T1_END) {
        int r = bid - WS_T0_END; int layer = r / 64; tile = r % 64;
        K = CDIM; N = CDIM; bxc = 8;
        W  = wo  + (size_t)layer * K * N;
        Th = woh + (size_t)layer * N * K; Tl = wol + (size_t)layer * N * K;
    } else if (bid < WS_T2_END) {
        int r = bid - WS_T1_END; int layer = r / 256; tile = r % 256;
        K = CDIM; N = FFDIM; bxc = 32;
        W  = wfc + (size_t)layer * K * N;
        Th = fch + (size_t)layer * N * K; Tl = fcl + (size_t)layer * N * K;
    } else if (bid < WS_T3_END) {
        int r = bid - WS_T2_END; int layer = r / 256; tile = r % 256;
        K = FFDIM; N = CDIM; bxc = 8;
        W  = wpr + (size_t)layer * K * N;
        Th = prh + (size_t)layer * N * K; Tl = prl + (size_t)layer * N * K;
    } else {
        tile = bid - WS_T3_END;
        K = CDIM; N = VDIM; bxc = 4;
        W = wlm; Th = lmh; Tl = lml;
    }
    int nx = (tile % bxc) * 32, kx = (tile / bxc) * 32;

    __shared__ float t[32][33];
    #pragma unroll
    for (int i = 0; i < 4; i++) {
        int k = kx + threadIdx.y + i * 8;
        t[threadIdx.y + i * 8][threadIdx.x] = W[(size_t)k * N + nx + threadIdx.x];
    }
    __syncthreads();
    #pragma unroll
    for (int i = 0; i < 4; i++) {
        int n = nx + threadIdx.y + i * 8;
        int k = kx + threadIdx.x;
        float v = t[threadIdx.x][threadIdx.y + i * 8];
        __half h, l; f16split(v, h, l);
        Th[(size_t)n * K + k] = h;
        Tl[(size_t)n * K + k] = l;
    }
}

// ---------------- embedding ----------------
__global__ void embed_kernel(const int* __restrict__ idx,
                             const float* __restrict__ tok,
                             const float* __restrict__ pos,
                             float* __restrict__ x) {
    int i = blockIdx.x * blockDim.x + threadIdx.x;
    if (i >= NTOK * CDIM) return;
    int row = i >> 8;
    int c   = i & (CDIM - 1);
    int t   = row & (TSEQ - 1);
    x[i] = tok[(size_t)idx[row] * CDIM + c] + pos[(size_t)t * CDIM + c];
}

// ---------------- layernorm -> single fp16 ----------------
__global__ void ln_kernel(const float* __restrict__ x,
                          const float* __restrict__ g,
                          const float* __restrict__ b,
                          __half* __restrict__ oh) {
    int row = blockIdx.x;
    int c   = threadIdx.x;
    float v = x[(size_t)row * CDIM + c];
    float s1 = warp_sum(v);
    float s2 = warp_sum(v * v);
    __shared__ float sh1[8], sh2[8];
    int w = c >> 5, lane = c & 31;
    if (lane == 0) { sh1[w] = s1; sh2[w] = s2; }
    __syncthreads();
    float t1 = 0.f, t2 = 0.f;
    #pragma unroll
    for (int i = 0; i < 8; i++) { t1 += sh1[i]; t2 += sh2[i]; }
    float mean = t1 * (1.0f / CDIM);
    float var  = t2 * (1.0f / CDIM) - mean * mean;
    float rstd = rsqrtf(var + 1e-5f);
    float o = (v - mean) * rstd * g[c] + b[c];
    oh[(size_t)row * CDIM + c] = __float2half_rn(o);
}

// ---------------- mma.sync fp16 2-term GEMM, 3-stage pipeline ----------------
// D = A @ (Bh + Bl)^T.  A single fp16; B fp16 hi/lo pair; fp32 accumulators.
// MODE 0: plain fp32   2: +bias +residual fp32
// MODE 3: +bias GELU -> fp16 single   4: +bias -> fp16 hi/lo pair
#define GBM 128
#define GBN 128
#define GBK 32
#define ROWB 80
#define TILE_HB (128 * ROWB)            // 10240 bytes per 128x32 fp16 tile
#define STAGE_B3 (3 * TILE_HB)          // A, Bh, Bl = 30720
#define GSMEM (3 * STAGE_B3)            // 3 stages = 92160 bytes

template<int MODE>
__global__ __launch_bounds__(256, 2)
void gemm_mma(const __half* __restrict__ A,
              const __half* __restrict__ Bh, const __half* __restrict__ Bl,
              const float* __restrict__ bias, const float* __restrict__ res,
              float* __restrict__ outF,
              __half* __restrict__ outH, __half* __restrict__ outL,
              int K, int No)
{
    extern __shared__ char smem[];
    uint32_t sU = smem_to_u32(smem);
    int tid  = threadIdx.x;
    int wid  = tid >> 5, lane = tid & 31;
    int warp_m = wid & 3, warp_n = wid >> 2;
    int m0 = blockIdx.y * GBM, n0 = blockIdx.x * GBN;

    float C[2][8][4];
    #pragma unroll
    for (int mt = 0; mt < 2; mt++)
        #pragma unroll
        for (int nt = 0; nt < 8; nt++)
            #pragma unroll
            for (int k = 0; k < 4; k++) C[mt][nt][k] = 0.f;

    int lr0 = tid >> 2,  lc0 = (tid & 3);
    int lr1 = (tid + 256) >> 2, lc1 = ((tid + 256) & 3);

    int nch = K >> 5;
    auto load_stage = [&](int ch, int buf) {
        int k0 = ch * GBK;
        uint32_t sb = sU + buf * STAGE_B3;
        {
            uint32_t so = lr0 * ROWB + lc0 * 16;
            cp16(sb + so,               A  + (size_t)(m0 + lr0) * K + k0 + lc0 * 8);
            cp16(sb + TILE_HB + so,     Bh + (size_t)(n0 + lr0) * K + k0 + lc0 * 8);
            cp16(sb + 2 * TILE_HB + so, Bl + (size_t)(n0 + lr0) * K + k0 + lc0 * 8);
        }
        {
            uint32_t so = lr1 * ROWB + lc1 * 16;
            cp16(sb + so,               A  + (size_t)(m0 + lr1) * K + k0 + lc1 * 8);
            cp16(sb + TILE_HB + so,     Bh + (size_t)(n0 + lr1) * K + k0 + lc1 * 8);
            cp16(sb + 2 * TILE_HB + so, Bl + (size_t)(n0 + lr1) * K + k0 + lc1 * 8);
        }
    };

    load_stage(0, 0);
    CP_COMMIT();
    if (nch > 1) { load_stage(1, 1); CP_COMMIT(); }

    int rin = lane & 7;
    int amat = lane >> 3;
    int bnt  = (lane >> 4) & 1;
    int bkh  = (lane >> 3) & 1;

    for (int ch = 0; ch < nch; ch++) {
        int buf = ch % 3;
        if (ch + 1 < nch) { CP_WAIT1(); } else { CP_WAIT0(); }
        __syncthreads();                 // stage ch ready; stage (ch+2)%3 free
        if (ch + 2 < nch) { load_stage(ch + 2, (ch + 2) % 3); CP_COMMIT(); }

        uint32_t sA  = sU + buf * STAGE_B3;
        uint32_t sBh = sA + TILE_HB;
        uint32_t sBl = sA + 2 * TILE_HB;

        #pragma unroll
        for (int s = 0; s < 2; s++) {
            uint32_t ah[2][4];
            #pragma unroll
            for (int mt = 0; mt < 2; mt++) {
                int row = warp_m * 32 + mt * 16 + (amat & 1) * 8 + rin;
                uint32_t off = row * ROWB + (amat >> 1) * 16 + s * 32;
                ldm4(sA + off, ah[mt][0], ah[mt][1], ah[mt][2], ah[mt][3]);
            }
            #pragma unroll
            for (int g = 0; g < 4; g++) {
                int row = warp_n * 64 + g * 16 + bnt * 8 + rin;
                uint32_t off = row * ROWB + bkh * 16 + s * 32;
                uint32_t bh[4], bl[4];
                ldm4(sBh + off, bh[0], bh[1], bh[2], bh[3]);
                ldm4(sBl + off, bl[0], bl[1], bl[2], bl[3]);
                #pragma unroll
                for (int mt = 0; mt < 2; mt++) {
                    mma16816(C[mt][2*g],   ah[mt], &bh[0]);
                    mma16816(C[mt][2*g],   ah[mt], &bl[0]);
                    mma16816(C[mt][2*g+1], ah[mt], &bh[2]);
                    mma16816(C[mt][2*g+1], ah[mt], &bl[2]);
                }
            }
        }
    }

    // ---- epilogue ----
    int rbase = m0 + warp_m * 32;
    int cbase = n0 + warp_n * 64;
    #pragma unroll
    for (int mt = 0; mt < 2; mt++) {
        #pragma unroll
        for (int nt = 0; nt < 8; nt++) {
            int row = rbase + mt * 16 + (lane >> 2);
            int col = cbase + nt * 8 + (lane & 3) * 2;
            const float* c = C[mt][nt];
            float2 b2 = make_float2(0.f, 0.f);
            if (MODE >= 2) b2 = *(const float2*)(bias + col);
            if (MODE == 4) {
                uint32_t hi, lo;
                hpack2(c[0] + b2.x, c[1] + b2.y, hi, lo);
                *(uint32_t*)(outH + (size_t)row * No + col) = hi;
                *(uint32_t*)(outL + (size_t)row * No + col) = lo;
                hpack2(c[2] + b2.x, c[3] + b2.y, hi, lo);
                *(uint32_t*)(outH + (size_t)(row + 8) * No + col) = hi;
                *(uint32_t*)(outL + (size_t)(row + 8) * No + col) = lo;
            } else if (MODE == 3) {
                *(uint32_t*)(outH + (size_t)row * No + col) =
                    hpack(gelu_f(c[0] + b2.x), gelu_f(c[1] + b2.y));
                *(uint32_t*)(outH + (size_t)(row + 8) * No + col) =
                    hpack(gelu_f(c[2] + b2.x), gelu_f(c[3] + b2.y));
            } else {
                float2 v0 = make_float2(c[0] + b2.x, c[1] + b2.y);
                float2 v1 = make_float2(c[2] + b2.x, c[3] + b2.y);
                if (MODE == 2) {
                    float2 r0 = *(const float2*)(res + (size_t)row * No + col);
                    float2 r1 = *(const float2*)(res + (size_t)(row + 8) * No + col);
                    v0.x += r0.x; v0.y += r0.y; v1.x += r1.x; v1.y += r1.y;
                }
                *(float2*)(outF + (size_t)row * No + col) = v0;
                *(float2*)(outF + (size_t)(row + 8) * No + col) = v1;
            }
        }
    }
}

// ---------------- flash attention on mma.sync (fp16 hi/lo 3-term) ----------------
// R5 structure (single-buffered K/V, static smem) — known-good perf.
#define AP 80
#define ATILE (64 * AP)            // 5120 bytes per 64x32 fp16 tile

__global__ __launch_bounds__(128)
void attn_mma(const __half* __restrict__ qkvH,
              const __half* __restrict__ qkvL,
              __half* __restrict__ y)
{
    __shared__ __align__(16) char sm[4 * ATILE];
    uint32_t sK = smem_to_u32(sm);          // Kh, Kl, Vh, Vl
    int tid = threadIdx.x, wid = tid >> 5, lane = tid & 31;
    int b = blockIdx.y >> 3, h = blockIdx.y & 7;
    int q0 = blockIdx.x * 64;
    size_t tokbase = (size_t)b * TSEQ * 768;
    const float qs = 0.17677669529663687f * 1.4426950408889634f;

    // ---- load Q tile (64x32 hi/lo), extract A-frags ----
    #pragma unroll
    for (int i = 0; i < 2; i++) {
        int u = tid + i * 128;
        int row = u >> 2, c = u & 3;
        size_t g = tokbase + (size_t)(q0 + row) * 768 + h * DHEAD + c * 8;
        *(uint4*)(sm + row * AP + c * 16)         = *(const uint4*)(qkvH + g);
        *(uint4*)(sm + ATILE + row * AP + c * 16) = *(const uint4*)(qkvL + g);
    }
    __syncthreads();
    uint32_t qh[2][4], ql[2][4];
    #pragma unroll
    for (int ks = 0; ks < 2; ks++) {
        uint32_t a = sK + (wid * 16 + (lane & 15)) * AP + ks * 32 + (lane >> 4) * 16;
        ldm4(a,         qh[ks][0], qh[ks][1], qh[ks][2], qh[ks][3]);
        ldm4(a + ATILE, ql[ks][0], ql[ks][1], ql[ks][2], ql[ks][3]);
    }

    float O[4][4];
    #pragma unroll
    for (int i = 0; i < 4; i++)
        #pragma unroll
        for (int j = 0; j < 4; j++) O[i][j] = 0.f;
    float m0 = -1e30f, m1 = -1e30f, l0 = 0.f, l1 = 0.f;

    int ntiles = blockIdx.x + 1;
    for (int kb = 0; kb < ntiles; kb++) {
        int j0 = kb * 64;
        __syncthreads();
        #pragma unroll
        for (int i = 0; i < 8; i++) {
            int u = i * 128 + tid;
            int bufi = u >> 8;
            int c = u & 255, row = c >> 2, cc = c & 3;
            size_t g = tokbase + (size_t)(j0 + row) * 768 + h * DHEAD + cc * 8;
            const __half* src;
            if      (bufi == 0) src = qkvH + g + CDIM;
            else if (bufi == 1) src = qkvL + g + CDIM;
            else if (bufi == 2) src = qkvH + g + 2 * CDIM;
            else                src = qkvL + g + 2 * CDIM;
            cp16(sK + bufi * ATILE + row * AP + cc * 16, src);
        }
        CP_COMMIT(); CP_WAIT0();
        __syncthreads();

        // ---- S = Q K^T (3-term) ----
        float sc[8][4];
        #pragma unroll
        for (int nt = 0; nt < 8; nt++)
            #pragma unroll
            for (int j = 0; j < 4; j++) sc[nt][j] = 0.f;
        #pragma unroll
        for (int ks = 0; ks < 2; ks++) {
            #pragma unroll
            for (int g = 0; g < 4; g++) {
                uint32_t addr = sK + (g * 16 + ((lane >> 4) & 1) * 8 + (lane & 7)) * AP
                              + ks * 32 + ((lane >> 3) & 1) * 16;
                uint32_t kh[4], kl[4];
                ldm4(addr,         kh[0], kh[1], kh[2], kh[3]);
                ldm4(addr + ATILE, kl[0], kl[1], kl[2], kl[3]);
                mma16816(sc[2*g],   qh[ks], &kh[0]);
                mma16816(sc[2*g],   qh[ks], &kl[0]);
                mma16816(sc[2*g],   ql[ks], &kh[0]);
                mma16816(sc[2*g+1], qh[ks], &kh[2]);
                mma16816(sc[2*g+1], qh[ks], &kl[2]);
                mma16816(sc[2*g+1], ql[ks], &kh[2]);
            }
        }

        // ---- causal mask on diagonal tile ----
        if (kb == blockIdx.x) {
            int qr = wid * 16 + (lane >> 2);
            #pragma unroll
            for (int nt = 0; nt < 8; nt++) {
                int kc = nt * 8 + (lane & 3) * 2;
                if (kc     > qr)     sc[nt][0] = -1e30f;
                if (kc + 1 > qr)     sc[nt][1] = -1e30f;
                if (kc     > qr + 8) sc[nt][2] = -1e30f;
                if (kc + 1 > qr + 8) sc[nt][3] = -1e30f;
            }
        }

        // ---- online softmax (base-2) ----
        float rm0 = -1e30f, rm1 = -1e30f;
        #pragma unroll
        for (int nt = 0; nt < 8; nt++) {
            rm0 = fmaxf(rm0, fmaxf(sc[nt][0], sc[nt][1]));
            rm1 = fmaxf(rm1, fmaxf(sc[nt][2], sc[nt][3]));
        }
        rm0 = fmaxf(rm0, __shfl_xor_sync(0xFFFFFFFFu, rm0, 1));
        rm0 = fmaxf(rm0, __shfl_xor_sync(0xFFFFFFFFu, rm0, 2));
        rm1 = fmaxf(rm1, __shfl_xor_sync(0xFFFFFFFFu, rm1, 1));
        rm1 = fmaxf(rm1, __shfl_xor_sync(0xFFFFFFFFu, rm1, 2));
        float m0n = fmaxf(m0, rm0), m1n = fmaxf(m1, rm1);
        float c0 = ex2f((m0 - m0n) * qs), c1 = ex2f((m1 - m1n) * qs);
        m0 = m0n; m1 = m1n;
        float mq0 = m0 * qs, mq1 = m1 * qs;
        float rs0 = 0.f, rs1 = 0.f;
        #pragma unroll
        for (int nt = 0; nt < 8; nt++) {
            sc[nt][0] = ex2f(fmaf(sc[nt][0], qs, -mq0));
            sc[nt][1] = ex2f(fmaf(sc[nt][1], qs, -mq0));
            sc[nt][2] = ex2f(fmaf(sc[nt][2], qs, -mq1));
            sc[nt][3] = ex2f(fmaf(sc[nt][3], qs, -mq1));
            rs0 += sc[nt][0] + sc[nt][1];
            rs1 += sc[nt][2] + sc[nt][3];
        }
        rs0 += __shfl_xor_sync(0xFFFFFFFFu, rs0, 1);
        rs0 += __shfl_xor_sync(0xFFFFFFFFu, rs0, 2);
        rs1 += __shfl_xor_sync(0xFFFFFFFFu, rs1, 1);
        rs1 += __shfl_xor_sync(0xFFFFFFFFu, rs1, 2);
        l0 = l0 * c0 + rs0;
        l1 = l1 * c1 + rs1;
        #pragma unroll
        for (int nt = 0; nt < 4; nt++) {
            O[nt][0] *= c0; O[nt][1] *= c0;
            O[nt][2] *= c1; O[nt][3] *= c1;
        }

        // ---- O += P V (3-term) ----
        #pragma unroll
        for (int ks = 0; ks < 4; ks++) {
            uint32_t ph[4], pl[4];
            hpack2(sc[2*ks][0],   sc[2*ks][1],   ph[0], pl[0]);
            hpack2(sc[2*ks][2],   sc[2*ks][3],   ph[1], pl[1]);
            hpack2(sc[2*ks+1][0], sc[2*ks+1][1], ph[2], pl[2]);
            hpack2(sc[2*ks+1][2], sc[2*ks+1][3], ph[3], pl[3]);
            #pragma unroll
            for (int g = 0; g < 2; g++) {
                uint32_t addr = sK + 2 * ATILE
                              + (16 * ks + ((lane >> 3) & 1) * 8 + (lane & 7)) * AP
                              + g * 32 + (lane >> 4) * 16;
                uint32_t vh[4], vl[4];
                ldm4t(addr,         vh[0], vh[1], vh[2], vh[3]);
                ldm4t(addr + ATILE, vl[0], vl[1], vl[2], vl[3]);
                mma16816(O[2*g],   ph, &vh[0]);
                mma16816(O[2*g],   ph, &vl[0]);
                mma16816(O[2*g],   pl, &vh[0]);
                mma16816(O[2*g+1], ph, &vh[2]);
                mma16816(O[2*g+1], ph, &vl[2]);
                mma16816(O[2*g+1], pl, &vh[2]);
            }
        }
    }

    // ---- normalize + write single fp16 ----
    float i0 = 1.0f / l0, i1 = 1.0f / l1;
    int r0 = q0 + wid * 16 + (lane >> 2);
    #pragma unroll
    for (int nt = 0; nt < 4; nt++) {
        int col = h * DHEAD + nt * 8 + (lane & 3) * 2;
        size_t g0 = (size_t)(b * TSEQ + r0) * CDIM + col;
        size_t g1 = g0 + (size_t)8 * CDIM;
        *(uint32_t*)(y + g0) = hpack(O[nt][0] * i0, O[nt][1] * i0);
        *(uint32_t*)(y + g1) = hpack(O[nt][2] * i1, O[nt][3] * i1);
    }
}

// ---------------- host orchestration (graph-capturable) ----------------
extern "C" void kernel_launch(void* const* d_in, const int* in_sizes, int n_in,
                              void* d_out, int out_size) {
    (void)in_sizes; (void)n_in; (void)out_size;
    const int*   idx   = (const int*)  d_in[0];
    const float* tok   = (const float*)d_in[1];
    const float* pos   = (const float*)d_in[2];
    const float* ln1g  = (const float*)d_in[3];
    const float* ln1b  = (const float*)d_in[4];
    const float* wqkv  = (const float*)d_in[5];
    const float* bqkv  = (const float*)d_in[6];
    const float* wo    = (const float*)d_in[7];
    const float* bo    = (const float*)d_in[8];
    const float* ln2g  = (const float*)d_in[9];
    const float* ln2b  = (const float*)d_in[10];
    const float* wfc   = (const float*)d_in[11];
    const float* bfc   = (const float*)d_in[12];
    const float* wpr   = (const float*)d_in[13];
    const float* bpr   = (const float*)d_in[14];
    const float* lnfg  = (const float*)d_in[15];
    const float* lnfb  = (const float*)d_in[16];
    const float* wlm   = (const float*)d_in[17];
    float* out = (float*)d_out;

    float *x;
    __half *qh, *ql_, *hbuf, *ybuf, *gbuf;
    __half *wqkvTh, *wqkvTl, *woTh, *woTl, *wfcTh, *wfcTl, *wprTh, *wprTl, *wlmTh, *wlmTl;
    cudaGetSymbolAddress((void**)&x,    g_x);
    cudaGetSymbolAddress((void**)&qh,   g_qkvh);
    cudaGetSymbolAddress((void**)&ql_,  g_qkvl);
    cudaGetSymbolAddress((void**)&hbuf, g_h);
    cudaGetSymbolAddress((void**)&ybuf, g_y);
    cudaGetSymbolAddress((void**)&gbuf, g_g);
    cudaGetSymbolAddress((void**)&wqkvTh, g_wqkvT_h);
    cudaGetSymbolAddress((void**)&wqkvTl, g_wqkvT_l);
    cudaGetSymbolAddress((void**)&woTh,   g_woT_h);
    cudaGetSymbolAddress((void**)&woTl,   g_woT_l);
    cudaGetSymbolAddress((void**)&wfcTh,  g_wfcT_h);
    cudaGetSymbolAddress((void**)&wfcTl,  g_wfcT_l);
    cudaGetSymbolAddress((void**)&wprTh,  g_wprT_h);
    cudaGetSymbolAddress((void**)&wprTl,  g_wprT_l);
    cudaGetSymbolAddress((void**)&wlmTh,  g_wlmT_h);
    cudaGetSymbolAddress((void**)&wlmTl,  g_wlmT_l);

    cudaFuncSetAttribute(gemm_mma<0>, cudaFuncAttributeMaxDynamicSharedMemorySize, GSMEM);
    cudaFuncSetAttribute(gemm_mma<2>, cudaFuncAttributeMaxDynamicSharedMemorySize, GSMEM);
    cudaFuncSetAttribute(gemm_mma<3>, cudaFuncAttributeMaxDynamicSharedMemorySize, GSMEM);
    cudaFuncSetAttribute(gemm_mma<4>, cudaFuncAttributeMaxDynamicSharedMemorySize, GSMEM);

    wsplit_all<<<WS_TOTAL, dim3(32, 8)>>>(
        wqkv, wo, wfc, wpr, wlm,
        wqkvTh, wqkvTl, woTh, woTl, wfcTh, wfcTl, wprTh, wprTl, wlmTh, wlmTl);

    embed_kernel<<<(NTOK * CDIM + 255) / 256, 256>>>(idx, tok, pos, x);

    dim3 gB(256);
    dim3 grid_qkv(3 * CDIM / GBN, NTOK / GBM);
    dim3 grid_prj(CDIM / GBN,     NTOK / GBM);
    dim3 grid_fc (FFDIM / GBN,    NTOK / GBM);
    dim3 grid_lm (VDIM / GBN,     NTOK / GBM);
    dim3 grid_att(TSEQ / 64, BATCH * HEADS);

    for (int l = 0; l < LAYERS; l++) {
        ln_kernel<<<NTOK, 256>>>(x, ln1g + l * CDIM, ln1b + l * CDIM, hbuf);
        gemm_mma<4><<<grid_qkv, gB, GSMEM>>>(
            hbuf,
            wqkvTh + (size_t)l * 3 * CDIM * CDIM, wqkvTl + (size_t)l * 3 * CDIM * CDIM,
            bqkv + (size_t)l * 3 * CDIM, nullptr, nullptr, qh, ql_,
            CDIM, 3 * CDIM);
        attn_mma<<<grid_att, 128>>>(qh, ql_, ybuf);
        gemm_mma<2><<<grid_prj, gB, GSMEM>>>(
            ybuf,
            woTh + (size_t)l * CDIM * CDIM, woTl + (size_t)l * CDIM * CDIM,
            bo + (size_t)l * CDIM, x, x, nullptr, nullptr,
            CDIM, CDIM);
        ln_kernel<<<NTOK, 256>>>(x, ln2g + l * CDIM, ln2b + l * CDIM, hbuf);
        gemm_mma<3><<<grid_fc, gB, GSMEM>>>(
            hbuf,
            wfcTh + (size_t)l * FFDIM * CDIM, wfcTl + (size_t)l * FFDIM * CDIM,
            bfc + (size_t)l * FFDIM, nullptr, nullptr, gbuf, nullptr,
            CDIM, FFDIM);
        gemm_mma<2><<<grid_prj, gB, GSMEM>>>(
            gbuf,
            wprTh + (size_t)l * CDIM * FFDIM, wprTl + (size_t)l * CDIM * FFDIM,
            bpr + (size_t)l * CDIM, x, x, nullptr, nullptr,
            FFDIM, CDIM);
    }

    ln_kernel<<<NTOK, 256>>>(x, lnfg, lnfb, hbuf);
    gemm_mma<0><<<grid_lm, gB, GSMEM>>>(
        hbuf, wlmTh, wlmTl,
        nullptr, nullptr, out, nullptr, nullptr,
        CDIM, VDIM);
}